// round 6
// baseline (speedup 1.0000x reference)
#include <cuda_runtime.h>
#include <cstdint>

// DWT_2D Haar: x (16,64,256,256) f32 -> (ll,lh,hl,hh) each (16,64,128,128).
// R6: smem-staged tiles written to GMEM via TMA bulk stores (cp.async.bulk
// SMEM->GMEM, 4KB per band per block) instead of per-thread STG — tests
// whether the TMA write path improves DRAM controller efficiency below the
// LTS cap.

#define BCN   1024
#define HDIM  256
#define WDIM  256
#define OH    128
#define OW    128

__device__ __forceinline__ uint32_t smem_u32(const void* p) {
    return (uint32_t)__cvta_generic_to_shared(p);
}

__global__ void __launch_bounds__(256)
dwt2d_haar_kernel(const float* __restrict__ x, float* __restrict__ out) {
    __shared__ __align__(128) float4 stage[4][256];   // [band][orow*32+g] -> 16KB

    unsigned b    = blockIdx.x;
    unsigned bc   = b >> 4;            // (b*c) slice, 0..1023
    unsigned rblk = b & 15u;           // 8-output-row block within slice

    unsigned t    = threadIdx.x;
    unsigned g    = t & 31u;           // 4 output cols (8 input cols)
    unsigned orow = t >> 5;            // 0..7

    // ---- compute: butterfly on one row-pair segment ----
    unsigned irow = (rblk * 8u + orow) * 2u;
    const float* base = x + (size_t)bc * (HDIM * WDIM) + (size_t)irow * WDIM + g * 8u;

    float4 r0a = *(const float4*)base;
    float4 r0b = *(const float4*)(base + 4);
    float4 r1a = *(const float4*)(base + WDIM);
    float4 r1b = *(const float4*)(base + WDIM + 4);

    float t0[8] = {r0a.x, r0a.y, r0a.z, r0a.w, r0b.x, r0b.y, r0b.z, r0b.w};
    float t1[8] = {r1a.x, r1a.y, r1a.z, r1a.w, r1b.x, r1b.y, r1b.z, r1b.w};

    float llv[4], lhv[4], hlv[4], hhv[4];
#pragma unroll
    for (int k = 0; k < 4; ++k) {
        float a = t0[2 * k], bb = t0[2 * k + 1];
        float c = t1[2 * k], d  = t1[2 * k + 1];
        float s0 = a + bb, d0 = a - bb;
        float s1 = c + d,  d1 = c - d;
        llv[k] = 0.5f * (s0 + s1);
        lhv[k] = 0.5f * (d0 + d1);
        hlv[k] = 0.5f * (s0 - s1);
        hhv[k] = 0.5f * (d0 - d1);
    }

    unsigned e = orow * 32u + g;
    stage[0][e] = make_float4(llv[0], llv[1], llv[2], llv[3]);
    stage[1][e] = make_float4(lhv[0], lhv[1], lhv[2], lhv[3]);
    stage[2][e] = make_float4(hlv[0], hlv[1], hlv[2], hlv[3]);
    stage[3][e] = make_float4(hhv[0], hhv[1], hhv[2], hhv[3]);

    __syncthreads();

    // ---- write: 4 TMA bulk stores, 4KB contiguous per band ----
    if (t == 0) {
        // Make generic-proxy smem writes visible to the async proxy.
        asm volatile("fence.proxy.async.shared::cta;" ::: "memory");

        const size_t bandstride = (size_t)BCN * OH * OW;
        size_t obase = (size_t)bc * (OH * OW) + (size_t)(rblk * 8u) * OW;

#pragma unroll
        for (int band = 0; band < 4; ++band) {
            float* dst = out + (size_t)band * bandstride + obase;
            uint32_t src = smem_u32(&stage[band][0]);
            asm volatile(
                "cp.async.bulk.global.shared::cta.bulk_group [%0], [%1], %2;"
                :: "l"(dst), "r"(src), "n"(4096)
                : "memory");
        }
        asm volatile("cp.async.bulk.commit_group;" ::: "memory");
        // Drain before CTA exit (smem is reclaimed at exit).
        asm volatile("cp.async.bulk.wait_group.read 0;" ::: "memory");
    }
}

extern "C" void kernel_launch(void* const* d_in, const int* in_sizes, int n_in,
                              void* d_out, int out_size) {
    const float* x = (const float*)d_in[0];
    float* out = (float*)d_out;
    dwt2d_haar_kernel<<<16384, 256>>>(x, out);
}

// round 7
// speedup vs baseline: 1.0012x; 1.0012x over previous
#include <cuda_runtime.h>

// DWT_2D Haar: x (16,64,256,256) f32 -> (ll,lh,hl,hh) each (16,64,128,128).
// R7: R5 smem-staged structure + Blackwell 256-bit vector ld/st
// (ld/st.global.v8.f32) to halve L1tex wavefronts and LSU issue per byte.

#define BCN   1024
#define HDIM  256
#define WDIM  256
#define OH    128
#define OW    128

__device__ __forceinline__ void ldg256(const float* p, float* r) {
    asm volatile("ld.global.v8.f32 {%0,%1,%2,%3,%4,%5,%6,%7}, [%8];"
                 : "=f"(r[0]), "=f"(r[1]), "=f"(r[2]), "=f"(r[3]),
                   "=f"(r[4]), "=f"(r[5]), "=f"(r[6]), "=f"(r[7])
                 : "l"(p));
}

__device__ __forceinline__ void stg256(float* p, const float4 a, const float4 b) {
    asm volatile("st.global.v8.f32 [%0], {%1,%2,%3,%4,%5,%6,%7,%8};"
                 :: "l"(p),
                    "f"(a.x), "f"(a.y), "f"(a.z), "f"(a.w),
                    "f"(b.x), "f"(b.y), "f"(b.z), "f"(b.w)
                 : "memory");
}

__global__ void __launch_bounds__(256)
dwt2d_haar_kernel(const float* __restrict__ x, float* __restrict__ out) {
    __shared__ __align__(32) float4 stage[4][256];   // [band][orow*32+g] -> 16KB

    unsigned b    = blockIdx.x;
    unsigned bc   = b >> 4;            // (b*c) slice, 0..1023
    unsigned rblk = b & 15u;           // 8-output-row block within slice

    unsigned t    = threadIdx.x;
    unsigned g    = t & 31u;           // 4 output cols (8 input cols = 32B)
    unsigned orow = t >> 5;            // 0..7

    // ---- compute: butterfly on one row-pair segment (2x 256-bit loads) ----
    unsigned irow = (rblk * 8u + orow) * 2u;
    const float* base = x + (size_t)bc * (HDIM * WDIM) + (size_t)irow * WDIM + g * 8u;

    float t0[8], t1[8];
    ldg256(base, t0);
    ldg256(base + WDIM, t1);

    float llv[4], lhv[4], hlv[4], hhv[4];
#pragma unroll
    for (int k = 0; k < 4; ++k) {
        float a = t0[2 * k], bb = t0[2 * k + 1];
        float c = t1[2 * k], d  = t1[2 * k + 1];
        float s0 = a + bb, d0 = a - bb;
        float s1 = c + d,  d1 = c - d;
        llv[k] = 0.5f * (s0 + s1);
        lhv[k] = 0.5f * (d0 + d1);
        hlv[k] = 0.5f * (s0 - s1);
        hhv[k] = 0.5f * (d0 - d1);
    }

    unsigned e = orow * 32u + g;
    stage[0][e] = make_float4(llv[0], llv[1], llv[2], llv[3]);
    stage[1][e] = make_float4(lhv[0], lhv[1], lhv[2], lhv[3]);
    stage[2][e] = make_float4(hlv[0], hlv[1], hlv[2], hlv[3]);
    stage[3][e] = make_float4(hhv[0], hhv[1], hhv[2], hhv[3]);

    __syncthreads();

    // ---- write: warp w -> band w/2, half w%2; 256-bit stores, 4KB/band ----
    unsigned w    = t >> 5;
    unsigned lane = t & 31u;
    unsigned band = w >> 1;
    unsigned half = w & 1u;

    const size_t bandstride = (size_t)BCN * OH * OW;
    float* dst = out + band * bandstride
                     + (size_t)bc * (OH * OW)
                     + (size_t)(rblk * 8u) * OW;

#pragma unroll
    for (int k = 0; k < 2; ++k) {
        // float4-slot index pair: each lane stores 32B (2 consecutive float4s)
        unsigned idx = half * 128u + (unsigned)k * 64u + lane * 2u;  // 0..254 even
        stg256(dst + idx * 4u, stage[band][idx], stage[band][idx + 1]);
    }
}

extern "C" void kernel_launch(void* const* d_in, const int* in_sizes, int n_in,
                              void* d_out, int out_size) {
    const float* x = (const float*)d_in[0];
    float* out = (float*)d_out;
    dwt2d_haar_kernel<<<16384, 256>>>(x, out);
}

// round 8
// speedup vs baseline: 1.0016x; 1.0004x over previous
#include <cuda_runtime.h>

// DWT_2D Haar: x (16,64,256,256) f32 -> (ll,lh,hl,hh) each (16,64,128,128),
// concatenated in d_out.
//
// Final form: direct 256-bit loads/stores, no smem, no sync. The kernel is
// DRAM-bound at the measured ~6.4 TB/s mixed read/write ceiling (~80% of
// 8 TB/s spec); traffic (536 MB) is compulsory, so this is the machine floor.
// (Falsified levers across R2-R7: .cs policy, MLP depth, write-burst
// locality, persistent+pipelined CTAs, TMA bulk store path, vector width.)

#define BCN   1024   // 16*64
#define HDIM  256
#define WDIM  256
#define OH    128
#define OW    128

__device__ __forceinline__ void ldg256(const float* p, float* r) {
    asm volatile("ld.global.v8.f32 {%0,%1,%2,%3,%4,%5,%6,%7}, [%8];"
                 : "=f"(r[0]), "=f"(r[1]), "=f"(r[2]), "=f"(r[3]),
                   "=f"(r[4]), "=f"(r[5]), "=f"(r[6]), "=f"(r[7])
                 : "l"(p));
}

__device__ __forceinline__ void stg256(float* p, const float* r) {
    asm volatile("st.global.v8.f32 [%0], {%1,%2,%3,%4,%5,%6,%7,%8};"
                 :: "l"(p),
                    "f"(r[0]), "f"(r[1]), "f"(r[2]), "f"(r[3]),
                    "f"(r[4]), "f"(r[5]), "f"(r[6]), "f"(r[7])
                 : "memory");
}

__global__ void __launch_bounds__(256)
dwt2d_haar_kernel(const float* __restrict__ x, float* __restrict__ out) {
    // tid = (bc << 11) | (i << 4) | g
    //   bc in [0,1024), i = output row in [0,128), g = group of 8 output cols in [0,16)
    unsigned tid = blockIdx.x * 256u + threadIdx.x;
    unsigned g  = tid & 15u;
    unsigned i  = (tid >> 4) & 127u;
    unsigned bc = tid >> 11;

    const float* base = x + (size_t)bc * (HDIM * WDIM) + (size_t)(2u * i) * WDIM + g * 16u;

    float t0[16], t1[16];
    ldg256(base,            t0);
    ldg256(base + 8,        t0 + 8);
    ldg256(base + WDIM,     t1);
    ldg256(base + WDIM + 8, t1 + 8);

    float llv[8], lhv[8], hlv[8], hhv[8];
#pragma unroll
    for (int k = 0; k < 8; ++k) {
        float a = t0[2 * k], b = t0[2 * k + 1];
        float c = t1[2 * k], d = t1[2 * k + 1];
        float s0 = a + b, d0 = a - b;
        float s1 = c + d, d1 = c - d;
        llv[k] = 0.5f * (s0 + s1);
        lhv[k] = 0.5f * (d0 + d1);
        hlv[k] = 0.5f * (s0 - s1);
        hhv[k] = 0.5f * (d0 - d1);
    }

    const size_t band = (size_t)BCN * OH * OW;              // 16,777,216
    float* o = out + (size_t)bc * (OH * OW) + (size_t)i * OW + g * 8u;

    stg256(o,            llv);
    stg256(o + band,     lhv);
    stg256(o + 2 * band, hlv);
    stg256(o + 3 * band, hhv);
}

extern "C" void kernel_launch(void* const* d_in, const int* in_sizes, int n_in,
                              void* d_out, int out_size) {
    const float* x = (const float*)d_in[0];
    float* out = (float*)d_out;
    // Total threads: 1024 * 128 * 16 = 2,097,152 -> 8192 blocks of 256
    dwt2d_haar_kernel<<<8192, 256>>>(x, out);
}